// round 9
// baseline (speedup 1.0000x reference)
#include <cuda_runtime.h>
#include <cuda_bf16.h>

// GaussianRender: 64 tiles (8x8) of 64x64 px, K=256 depth-sorted gaussians/tile.
// alpha = clip(op*prob, 0.01, 0.99). Gaussians provably far from a PIXEL BAND
// (Schur bound: log2(a) <= lop + min(e*mdx^2/cov_xx, e*mdy^2/cov_yy)) contribute
// exactly alpha=0.01 to every band pixel; a run of m far gaussians has closed
// form  acc += q*T0*S1 - q^2*S2rel,  T -= q*m  (pixel-independent sums).
//
// R9: streams are built PER 8-ROW BAND (8 per tile), shrinking nears ~3x.
// Gap sums come from per-tile exclusive prefix sums of (c, j*c): O(1)/entry.
// Entry = [merged run prefix (7 u64) | near gaussian (9 u64)] = 128B,
// trailing gap closed by a dummy near (k=0, colors=0) -> branch-free render.

#define KG     256
#define WIMG   512
#define NB     8             // bands per tile (8 rows each)
#define EU     16            // u64 per entry
#define MAXE   257           // worst-case entries per band
#define SENT   32            // entries cached in render smem

typedef unsigned long long u64;
union F2U { float2 f; u64 u; };

__device__ __align__(16) u64 g_ent[64][NB][MAXE * EU];
__device__ int g_cnt[64][NB];

__device__ __forceinline__ u64 pk(float a, float b) { F2U t; t.f = make_float2(a, b); return t.u; }
__device__ __forceinline__ u64 ffma2(u64 a, u64 b, u64 c) {
    u64 d; asm("fma.rn.f32x2 %0, %1, %2, %3;" : "=l"(d) : "l"(a), "l"(b), "l"(c)); return d;
}
__device__ __forceinline__ u64 fmul2(u64 a, u64 b) {
    u64 d; asm("mul.rn.f32x2 %0, %1, %2;" : "=l"(d) : "l"(a), "l"(b)); return d;
}
__device__ __forceinline__ u64 fadd2(u64 a, u64 b) {
    u64 d; asm("add.rn.f32x2 %0, %1, %2;" : "=l"(d) : "l"(a), "l"(b)); return d;
}
__device__ __forceinline__ float ex2f(float x) {
    float y; asm("ex2.approx.f32 %0, %1;" : "=f"(y) : "f"(x)); return y;
}
__device__ __forceinline__ float lg2f(float x) {
    float y; asm("lg2.approx.f32 %0, %1;" : "=f"(y) : "f"(x)); return y;
}
__device__ __forceinline__ float clampa(float a) { return fminf(fmaxf(a, 0.01f), 0.99f); }
__device__ __forceinline__ float wscan_inc(float v, int lane) {
    #pragma unroll
    for (int o = 1; o < 32; o <<= 1) {
        const float n = __shfl_up_sync(0xffffffffu, v, o);
        if (lane >= o) v += n;
    }
    return v;
}

// ===================== Kernel A: per-band stream build =====================
__global__ __launch_bounds__(256, 4)
void build_kernel(const float* __restrict__ mu,
                  const float* __restrict__ cov,
                  const float* __restrict__ opac,
                  const float* __restrict__ col,
                  const int*   __restrict__ tidx)
{
    __shared__ float E1r[KG + 1], E1g[KG + 1], E1b[KG + 1];
    __shared__ float E2r[KG + 1], E2g[KG + 1], E2b[KG + 1];
    __shared__ float wsum[6][8];
    __shared__ unsigned int wmask[8];
    __shared__ int sbase[8];
    __shared__ int snears[KG];
    __shared__ int s_nn;

    const int t    = blockIdx.x;     // tile 0..63
    const int tx   = t & 7;
    const int ty   = t >> 3;
    const int tid  = threadIdx.x;    // 0..255 = gaussian slot
    const int lane = tid & 31;
    const int warp = tid >> 5;

    const float x0 = (float)(tx * 64) + 0.5f, x1 = x0 + 63.0f;

    // ---- phase 1: per-gaussian params (kept in registers) ----
    float nmx, nmy, k1, k2, k3, lop, cr, cg, cb;
    float covxx, covyy, my_;
    float bxp;   // precomputed x-part of the Schur bound
    {
        const int g = tidx[t * KG + tid];
        const float4 cv = *(const float4*)(cov + g * 4);
        const float2 m  = *(const float2*)(mu + g * 2);
        const float det = fmaxf(fmaf(cv.x, cv.w, -cv.y * cv.z), 1e-6f);
        const float inv = 1.0f / det;
        const float e  = -0.7213475204444817f;   // -0.5 * log2(e)
        k1 = e * cv.w * inv;
        k2 = -e * (cv.y + cv.z) * inv;
        k3 = e * cv.x * inv;
        lop = lg2f(opac[g]);
        nmx = -m.x; nmy = -m.y; my_ = m.y;
        covxx = cv.x; covyy = cv.w;
        cr = col[g * 3 + 0];
        cg = col[g * 3 + 1];
        cb = col[g * 3 + 2];

        const float dlo = x0 - m.x, dhi = x1 - m.x;
        const float mdx = fmaxf(fmaxf(dlo, -dhi), 0.0f);
        bxp = __fdividef(e * mdx * mdx, covxx) + lop;  // band-independent part
    }

    // ---- phase 2: exclusive prefix sums of (c, j*c) ----
    {
        const float fj = (float)tid;
        float v[6] = { cr, cg, cb, fj * cr, fj * cg, fj * cb };
        float inc[6];
        #pragma unroll
        for (int q = 0; q < 6; ++q) {
            inc[q] = wscan_inc(v[q], lane);
            if (lane == 31) wsum[q][warp] = inc[q];
        }
        __syncthreads();
        float off[6] = {0.f, 0.f, 0.f, 0.f, 0.f, 0.f};
        #pragma unroll
        for (int w = 0; w < 8; ++w) {
            if (w < warp) {
                #pragma unroll
                for (int q = 0; q < 6; ++q) off[q] += wsum[q][w];
            }
        }
        E1r[tid] = off[0] + inc[0] - v[0];
        E1g[tid] = off[1] + inc[1] - v[1];
        E1b[tid] = off[2] + inc[2] - v[2];
        E2r[tid] = off[3] + inc[3] - v[3];
        E2g[tid] = off[4] + inc[4] - v[4];
        E2b[tid] = off[5] + inc[5] - v[5];
        if (tid == KG - 1) {
            E1r[KG] = off[0] + inc[0];
            E1g[KG] = off[1] + inc[1];
            E1b[KG] = off[2] + inc[2];
            E2r[KG] = off[3] + inc[3];
            E2g[KG] = off[4] + inc[4];
            E2b[KG] = off[5] + inc[5];
        }
    }
    __syncthreads();

    const float e = -0.7213475204444817f;
    const float q = 0.01f;

    // ---- phase 3: per-band streams ----
    for (int b = 0; b < NB; ++b) {
        const float yb0 = (float)(ty * 64 + b * 8) + 0.5f;
        const float yb1 = yb0 + 7.0f;
        const float elo = yb0 - my_, ehi = yb1 - my_;
        const float mdy = fmaxf(fmaxf(elo, -ehi), 0.0f);
        const float by = __fdividef(e * mdy * mdy, covyy) + lop;
        const bool isNear = !(fminf(bxp, by) < (-6.6438561897747395f - 0.01f));

        const unsigned int mask = __ballot_sync(0xffffffffu, isNear);
        if (lane == 0) wmask[warp] = mask;
        __syncthreads();
        if (tid == 0) {
            int a = 0;
            #pragma unroll
            for (int w = 0; w < 8; ++w) { sbase[w] = a; a += __popc(wmask[w]); }
            s_nn = a;
        }
        __syncthreads();
        int rank = -1;
        if (isNear) {
            rank = sbase[warp] + __popc(mask & ((1u << lane) - 1u));
            snears[rank] = tid;
        }
        __syncthreads();
        const int nn = s_nn;

        if (isNear) {
            const int start = (rank == 0) ? 0 : snears[rank - 1] + 1;
            const float fs = (float)start;
            const float S1r = E1r[tid] - E1r[start];
            const float S1g = E1g[tid] - E1g[start];
            const float S1b = E1b[tid] - E1b[start];
            const float S2r = (E2r[tid] - E2r[start]) - fs * S1r;
            const float S2g = (E2g[tid] - E2g[start]) - fs * S1g;
            const float S2b = (E2b[tid] - E2b[start]) - fs * S1b;
            const float cm  = (float)(tid - start);
            u64* p = g_ent[t][b] + rank * EU;
            p[0]  = pk(q * S1r, q * S1r);
            p[1]  = pk(q * S1g, q * S1g);
            p[2]  = pk(q * S1b, q * S1b);
            p[3]  = pk(-q * q * S2r, -q * q * S2r);
            p[4]  = pk(-q * q * S2g, -q * q * S2g);
            p[5]  = pk(-q * q * S2b, -q * q * S2b);
            p[6]  = pk(-q * cm, -q * cm);
            p[7]  = pk(nmx, nmx);
            p[8]  = pk(nmy, nmy);
            p[9]  = pk(k1, k1);
            p[10] = pk(k2, k2);
            p[11] = pk(k3, k3);
            p[12] = pk(lop, lop);
            p[13] = pk(cr, cr);
            p[14] = pk(cg, cg);
            p[15] = pk(cb, cb);
        }
        if (tid == 0) {
            // trailing entry: final gap + dummy near (zeros)
            const int start = (nn == 0) ? 0 : snears[nn - 1] + 1;
            const float fs = (float)start;
            const float S1r = E1r[KG] - E1r[start];
            const float S1g = E1g[KG] - E1g[start];
            const float S1b = E1b[KG] - E1b[start];
            const float S2r = (E2r[KG] - E2r[start]) - fs * S1r;
            const float S2g = (E2g[KG] - E2g[start]) - fs * S1g;
            const float S2b = (E2b[KG] - E2b[start]) - fs * S1b;
            const float cm  = (float)(KG - start);
            u64* p = g_ent[t][b] + nn * EU;
            p[0] = pk(q * S1r, q * S1r);
            p[1] = pk(q * S1g, q * S1g);
            p[2] = pk(q * S1b, q * S1b);
            p[3] = pk(-q * q * S2r, -q * q * S2r);
            p[4] = pk(-q * q * S2g, -q * q * S2g);
            p[5] = pk(-q * q * S2b, -q * q * S2b);
            p[6] = pk(-q * cm, -q * cm);
            #pragma unroll
            for (int r = 7; r < 16; ++r) p[r] = 0ull;
            g_cnt[t][b] = nn + 1;
        }
        __syncthreads();   // protect wmask/snears reuse
    }
}

// ===================== Kernel B: branch-free band render =====================
// entry as ulonglong2[8]:
//  v0={s1r,s1g} v1={s1b,s2r} v2={s2g,s2b} v3={scnt,-mx}
//  v4={-my,k1}  v5={k2,k3}   v6={lop,cr}  v7={cg,cb}
#define ENT_BODY(P)                                                          \
    {                                                                        \
        const ulonglong2 v0 = (P)[0], v1 = (P)[1], v2 = (P)[2], v3 = (P)[3]; \
        const ulonglong2 v4 = (P)[4], v5 = (P)[5], v6 = (P)[6], v7 = (P)[7]; \
        /* run prefixes */                                                   \
        aR0 = ffma2(trA, v0.x, aR0);  aR0 = fadd2(aR0, v1.y);                \
        aG0 = ffma2(trA, v0.y, aG0);  aG0 = fadd2(aG0, v2.x);                \
        aB0 = ffma2(trA, v1.x, aB0);  aB0 = fadd2(aB0, v2.y);                \
        trA = fadd2(trA, v3.x);                                              \
        aR1 = ffma2(trB, v0.x, aR1);  aR1 = fadd2(aR1, v1.y);                \
        aG1 = ffma2(trB, v0.y, aG1);  aG1 = fadd2(aG1, v2.x);                \
        aB1 = ffma2(trB, v1.x, aB1);  aB1 = fadd2(aB1, v2.y);                \
        trB = fadd2(trB, v3.x);                                              \
        /* near: dx-part shared by all 4 pixels */                           \
        const u64 dx2 = fadd2(px2, v3.y);                                    \
        const u64 t0  = fmul2(v4.y, dx2);                                    \
        const u64 u2  = ffma2(t0, dx2, v6.x);                                \
        const u64 kx2 = fmul2(v5.x, dx2);                                    \
        const u64 dyA = fadd2(pyA, v4.x);                                    \
        const u64 qA  = ffma2(v5.y, dyA, kx2);                               \
        const u64 pwA = ffma2(dyA, qA, u2);                                  \
        const u64 dyB = fadd2(pyB, v4.x);                                    \
        const u64 qB  = ffma2(v5.y, dyB, kx2);                               \
        const u64 pwB = ffma2(dyB, qB, u2);                                  \
        F2U PA, PB; PA.u = pwA; PB.u = pwB;                                  \
        F2U alA, alB;                                                        \
        alA.f.x = clampa(ex2f(PA.f.x));                                      \
        alA.f.y = clampa(ex2f(PA.f.y));                                      \
        alB.f.x = clampa(ex2f(PB.f.x));                                      \
        alB.f.y = clampa(ex2f(PB.f.y));                                      \
        const u64 wvA = fmul2(alA.u, trA);                                   \
        trA = ffma2(alA.u, m1, trA);                                         \
        const u64 wvB = fmul2(alB.u, trB);                                   \
        trB = ffma2(alB.u, m1, trB);                                         \
        aR0 = ffma2(wvA, v6.y, aR0);                                         \
        aG0 = ffma2(wvA, v7.x, aG0);                                         \
        aB0 = ffma2(wvA, v7.y, aB0);                                         \
        aR1 = ffma2(wvB, v6.y, aR1);                                         \
        aG1 = ffma2(wvB, v7.x, aG1);                                         \
        aB1 = ffma2(wvB, v7.y, aB1);                                         \
    }

__global__ __launch_bounds__(128)
void render_kernel(float* __restrict__ out)
{
    __shared__ __align__(16) u64 sent[SENT * EU];   // 4 KB

    const int bid = blockIdx.x;
    const int t   = bid >> 3;        // tile
    const int b   = bid & 7;         // band (8 rows)
    const int tx  = t & 7;
    const int ty  = t >> 3;
    const int tid = threadIdx.x;

    const int cnt = g_cnt[t][b];
    const u64* gsrc = g_ent[t][b];
    const int ns = (cnt < SENT) ? cnt : SENT;
    {
        const ulonglong2* s2p = (const ulonglong2*)gsrc;
        ulonglong2* d2p = (ulonglong2*)sent;
        const int n2 = ns * (EU / 2);
        for (int i = tid; i < n2; i += 128) d2p[i] = s2p[i];
    }
    __syncthreads();

    // 4 px/thread: column lx, rows b*8 + h*4 + {0,1,2,3}
    const int lx = tid & 63;
    const int h  = tid >> 6;
    const float px  = (float)(tx * 64 + lx) + 0.5f;
    const float py0 = (float)(ty * 64 + b * 8 + h * 4) + 0.5f;
    const u64 px2 = pk(px, px);
    const u64 pyA = pk(py0, py0 + 1.0f);
    const u64 pyB = pk(py0 + 2.0f, py0 + 3.0f);
    const u64 m1  = pk(-1.0f, -1.0f);

    u64 aR0 = 0, aG0 = 0, aB0 = 0, aR1 = 0, aG1 = 0, aB1 = 0;
    u64 trA = pk(1.0f, 1.0f), trB = pk(1.0f, 1.0f);

    const ulonglong2* p = (const ulonglong2*)sent;
    for (int e = 0; e < ns; ++e, p += 8) ENT_BODY(p)
    if (cnt > SENT) {
        const ulonglong2* pg = (const ulonglong2*)(gsrc + SENT * EU);
        for (int e = SENT; e < cnt; ++e, pg += 8) ENT_BODY(pg)
    }

    // write 4 pixels
    const int gx = tx * 64 + lx;
    const int gy = ty * 64 + b * 8 + h * 4;
    F2U R0, G0, B0, R1, G1, B1;
    R0.u = aR0; G0.u = aG0; B0.u = aB0;
    R1.u = aR1; G1.u = aG1; B1.u = aB1;
    float* o = out + ((size_t)gy * WIMG + gx) * 3;
    o[0] = R0.f.x; o[1] = G0.f.x; o[2] = B0.f.x;  o += WIMG * 3;
    o[0] = R0.f.y; o[1] = G0.f.y; o[2] = B0.f.y;  o += WIMG * 3;
    o[0] = R1.f.x; o[1] = G1.f.x; o[2] = B1.f.x;  o += WIMG * 3;
    o[0] = R1.f.y; o[1] = G1.f.y; o[2] = B1.f.y;
}

extern "C" void kernel_launch(void* const* d_in, const int* in_sizes, int n_in,
                              void* d_out, int out_size)
{
    const float* mu   = (const float*)d_in[0];
    const float* cov  = (const float*)d_in[1];
    const float* opac = (const float*)d_in[2];
    const float* col  = (const float*)d_in[3];
    const int*   tidx = (const int*)  d_in[4];
    float* out = (float*)d_out;

    build_kernel<<<64, 256>>>(mu, cov, opac, col, tidx);
    render_kernel<<<512, 128>>>(out);
}